// round 17
// baseline (speedup 1.0000x reference)
#include <cuda_runtime.h>
#include <cuda_bf16.h>
#include <cuda_fp16.h>
#include <math.h>
#include <stdint.h>

// ---------------------------------------------------------------------------
// Problem constants
// ---------------------------------------------------------------------------
#define BB   512
#define HH   128
#define WW   128
#define CONVN 16129
#define DIM  4096
#define KDIM 4096
#define OUTN (BB * DIM)

// ---------------------------------------------------------------------------
// Scratch (__device__ globals; no cudaMalloc allowed)
// ---------------------------------------------------------------------------
__device__ float g_c[BB];
__device__ __half g_ah[3][OUTN];      // fp16 act1..act3
// partials: fidA blocks (20) x 6 dots at [b*6]; GEMM blocks (128) x 4 dots at
// [256 + b*4]
__device__ float g_partials[1024];
__device__ unsigned int g_ticket;     // zero-init; reset by finalizer

// ---------------------------------------------------------------------------
// PTX helpers (plain-PTX, valid on non-'a' targets)
// ---------------------------------------------------------------------------
__device__ __forceinline__ uint32_t smem_to_u32(const void* p) {
    uint32_t a;
    asm("{ .reg .u64 t; cvta.to.shared.u64 t, %1; cvt.u32.u64 %0, t; }"
        : "=r"(a) : "l"(p));
    return a;
}
__device__ __forceinline__ void cpasync16(uint32_t dst, const void* gsrc) {
    asm volatile("cp.async.cg.shared.global [%0], [%1], 16;"
                 :: "r"(dst), "l"(__cvta_generic_to_global(gsrc)) : "memory");
}
#define CP_COMMIT() asm volatile("cp.async.commit_group;" ::: "memory")
template <int N>
__device__ __forceinline__ void cp_wait() {
    asm volatile("cp.async.wait_group %0;" :: "n"(N) : "memory");
}
__device__ __forceinline__ void ldsm_x4(uint32_t r[4], uint32_t addr) {
    asm volatile("ldmatrix.sync.aligned.m8n8.x4.shared.b16 {%0,%1,%2,%3}, [%4];"
                 : "=r"(r[0]), "=r"(r[1]), "=r"(r[2]), "=r"(r[3]) : "r"(addr));
}
__device__ __forceinline__ void mma16816h(float d[4], const uint32_t a[4],
                                          uint32_t b0, uint32_t b1) {
    asm volatile(
        "mma.sync.aligned.m16n8k16.row.col.f32.f16.f16.f32 "
        "{%0,%1,%2,%3}, {%4,%5,%6,%7}, {%8,%9}, {%0,%1,%2,%3};"
        : "+f"(d[0]), "+f"(d[1]), "+f"(d[2]), "+f"(d[3])
        : "r"(a[0]), "r"(a[1]), "r"(a[2]), "r"(a[3]), "r"(b0), "r"(b1));
}
__device__ __forceinline__ float tanh_approx(float x) {
    float r;
    asm("tanh.approx.f32 %0, %1;" : "=f"(r) : "f"(x));
    return r;
}

// ---------------------------------------------------------------------------
// 1) Conv 2x2 valid + bias + sigmoid + mean -> g_c[n]
// ---------------------------------------------------------------------------
__global__ void __launch_bounds__(256)
conv_kernel(const float* __restrict__ x,
            const float* __restrict__ cw,
            const float* __restrict__ cb,
            float* __restrict__ cOut) {
    const int n = blockIdx.x;
    const float* xp = x + n * HH * WW;
    const float w00 = 0.5f * cw[0], w01 = 0.5f * cw[1];
    const float w10 = 0.5f * cw[2], w11 = 0.5f * cw[3];
    const float bias = 0.5f * cb[0];
    float s = 0.0f;
    for (int idx = threadIdx.x; idx < 127 * 32; idx += 256) {
        const int i = idx >> 5;
        const int j = (idx & 31) * 4;
        const float* r0 = xp + i * WW + j;
        const float* r1 = r0 + WW;
        float4 a = *(const float4*)r0;
        float4 b = *(const float4*)r1;
        float a4 = 0.0f, b4 = 0.0f;
        if (j + 4 < WW) { a4 = r0[4]; b4 = r1[4]; }
        float x0[5] = {a.x, a.y, a.z, a.w, a4};
        float x1[5] = {b.x, b.y, b.z, b.w, b4};
        #pragma unroll
        for (int k = 0; k < 4; k++) {
            if (j + k < 127) {
                float hv = x0[k] * w00 + x0[k + 1] * w01
                         + x1[k] * w10 + x1[k + 1] * w11 + bias;
                s += tanh_approx(hv);
            }
        }
    }
    __shared__ float red[256];
    red[threadIdx.x] = s;
    __syncthreads();
    #pragma unroll
    for (int off = 128; off > 0; off >>= 1) {
        if (threadIdx.x < off) red[threadIdx.x] += red[threadIdx.x + off];
        __syncthreads();
    }
    if (threadIdx.x == 0)
        cOut[n] = 0.5f + 0.5f * (red[0] / (float)CONVN);
}

// ---------------------------------------------------------------------------
// 2) Fused attention + Layer 1 -> fp16 act1.  8 outputs/thread, uint4 stores.
// ---------------------------------------------------------------------------
__global__ void attn_layer1_kernel(const float* __restrict__ c,
                                   const float* __restrict__ rot,
                                   const float* __restrict__ ent,
                                   const float* __restrict__ W1,
                                   const float* __restrict__ b1,
                                   __half* __restrict__ oh) {
    const int i = blockIdx.x >> 1;
    const int j0 = (blockIdx.x & 1) * 2048 + threadIdx.x * 8;
    const int t = threadIdx.x;

    __shared__ float cs[BB];
    __shared__ float wred[8][2];
    __shared__ float aI;

    cs[t] = c[t];
    cs[t + 256] = c[t + 256];
    __syncthreads();

    const float e = ent[0];
    const float qi = cs[i] * rot[0];

    float v0 = qi * cs[t] * e, v1 = qi * cs[t + 256] * e;
    float mx = fmaxf(v0, v1);
    #pragma unroll
    for (int off = 16; off > 0; off >>= 1)
        mx = fmaxf(mx, __shfl_xor_sync(0xFFFFFFFFu, mx, off));
    if ((t & 31) == 0) wred[t >> 5][0] = mx;
    __syncthreads();
    float m = wred[0][0];
    #pragma unroll
    for (int w = 1; w < 8; w++) m = fmaxf(m, wred[w][0]);

    float e0 = __expf(v0 - m), e1 = __expf(v1 - m);
    float se = e0 + e1;
    float sa = e0 * cs[t] + e1 * cs[t + 256];
    #pragma unroll
    for (int off = 16; off > 0; off >>= 1) {
        se += __shfl_xor_sync(0xFFFFFFFFu, se, off);
        sa += __shfl_xor_sync(0xFFFFFFFFu, sa, off);
    }
    if ((t & 31) == 0) { wred[t >> 5][0] = se; wred[t >> 5][1] = sa; }
    __syncthreads();
    if (t == 0) {
        float tse = 0.0f, tsa = 0.0f;
        #pragma unroll
        for (int w = 0; w < 8; w++) { tse += wred[w][0]; tsa += wred[w][1]; }
        aI = tsa / tse;
    }
    __syncthreads();

    const float a = aI;
    float4 wv0 = *(const float4*)(W1 + j0);
    float4 wv1 = *(const float4*)(W1 + j0 + 4);
    float4 bv0 = *(const float4*)(b1 + j0);
    float4 bv1 = *(const float4*)(b1 + j0 + 4);
    float o[8];
    o[0] = tanhf(fmaf(a, wv0.x, bv0.x));
    o[1] = tanhf(fmaf(a, wv0.y, bv0.y));
    o[2] = tanhf(fmaf(a, wv0.z, bv0.z));
    o[3] = tanhf(fmaf(a, wv0.w, bv0.w));
    o[4] = tanhf(fmaf(a, wv1.x, bv1.x));
    o[5] = tanhf(fmaf(a, wv1.y, bv1.y));
    o[6] = tanhf(fmaf(a, wv1.z, bv1.z));
    o[7] = tanhf(fmaf(a, wv1.w, bv1.w));
    __half2 h0 = __floats2half2_rn(o[0], o[1]);
    __half2 h1 = __floats2half2_rn(o[2], o[3]);
    __half2 h2 = __floats2half2_rn(o[4], o[5]);
    __half2 h3 = __floats2half2_rn(o[6], o[7]);
    uint4 pack;
    pack.x = *(uint32_t*)&h0; pack.y = *(uint32_t*)&h1;
    pack.z = *(uint32_t*)&h2; pack.w = *(uint32_t*)&h3;
    *(uint4*)(oh + (size_t)i * DIM + j0) = pack;
}

// ---------------------------------------------------------------------------
// 3) HMMA GEMM + bias + tanh; in-kernel W fp32->fp16; ONE sync per 2 kt.
//    Grid is 1D: blocks [0,128) do GEMM (bid>>5 = m-tile, bid&31 = n-tile).
//    If wout != null (gemm3): blocks [128,148) compute the 6 act1-3 fidelity
//    dots concurrently; GEMM blocks accumulate the 4 act4 dots in-register in
//    the epilogue; the last of 148 blocks finalizes the weight matrix.
// ---------------------------------------------------------------------------
#define KT      64
#define NT      (KDIM / KT)             // 64
#define SROW    72                      // padded row stride in halves (144 B)
#define TILE_B  (128 * SROW * 2)        // 18432 B
#define NASLOT  6
#define WF_OFF  (NASLOT * TILE_B)       // 110592
#define BIAS_OFF (WF_OFF + 4 * TILE_B)  // 184320
#define SMEM_REQ (BIAS_OFF + 512)

__global__ void __launch_bounds__(512, 1)
gemm_mma_kernel(const __half* __restrict__ Ah,
                const float* __restrict__ W,    // fp32 weights, row-major
                const float* __restrict__ bias,
                float* __restrict__ C,          // may be null
                __half* __restrict__ Ch,        // may be null
                const __half* __restrict__ f1,  // act1 (fid) or null
                const __half* __restrict__ f2,
                const __half* __restrict__ f3,
                float* __restrict__ wout) {     // non-null => fid mode
    extern __shared__ __align__(16) char smem[];
    const uint32_t sbase = smem_to_u32(smem);
    float* biasS = (float*)(smem + BIAS_OFF);

    const int t = threadIdx.x;
    const int lane = t & 31;
    const int warp = t >> 5;            // 0..15
    const int bid = blockIdx.x;

    __shared__ float ws4[16][6];
    __shared__ unsigned int lastFlag;
    __shared__ double dots[10];

    // ---------------- fidA blocks (acts 1-3, 6 dots) ----------------
    if (wout != nullptr && bid >= 128) {
        const int fb = bid - 128;       // 0..19
        float s[6];
        #pragma unroll
        for (int k = 0; k < 6; k++) s[k] = 0.0f;
        const int stride = 20 * 512;
        for (int idx = fb * 512 + t; idx < OUTN / 8; idx += stride) {
            uint4 u1 = ((const uint4*)f1)[idx];
            uint4 u2 = ((const uint4*)f2)[idx];
            uint4 u3 = ((const uint4*)f3)[idx];
            const uint32_t* p1 = (const uint32_t*)&u1;
            const uint32_t* p2 = (const uint32_t*)&u2;
            const uint32_t* p3 = (const uint32_t*)&u3;
            #pragma unroll
            for (int q = 0; q < 4; q++) {
                float2 x1 = __half22float2(*(const __half2*)&p1[q]);
                float2 x2 = __half22float2(*(const __half2*)&p2[q]);
                float2 x3 = __half22float2(*(const __half2*)&p3[q]);
                s[0] += x1.x * x1.x + x1.y * x1.y;
                s[1] += x1.x * x2.x + x1.y * x2.y;
                s[2] += x1.x * x3.x + x1.y * x3.y;
                s[3] += x2.x * x2.x + x2.y * x2.y;
                s[4] += x2.x * x3.x + x2.y * x3.y;
                s[5] += x3.x * x3.x + x3.y * x3.y;
            }
        }
        #pragma unroll
        for (int k = 0; k < 6; k++)
            #pragma unroll
            for (int off = 16; off > 0; off >>= 1)
                s[k] += __shfl_down_sync(0xFFFFFFFFu, s[k], off);
        if (lane == 0)
            #pragma unroll
            for (int k = 0; k < 6; k++) ws4[warp][k] = s[k];
        __syncthreads();
        if (t == 0) {
            #pragma unroll
            for (int k = 0; k < 6; k++) {
                float acc = 0.0f;
                for (int w = 0; w < 16; w++) acc += ws4[w][k];
                g_partials[fb * 6 + k] = acc;
            }
            __threadfence();
            unsigned int v = atomicAdd(&g_ticket, 1u);
            lastFlag = (v == 147u) ? 1u : 0u;
        }
        __syncthreads();
        if (lastFlag == 0u) return;
        goto finalize;
    }

    // ---------------- GEMM blocks ----------------
    {
    const int mw = warp >> 2;           // 0..3
    const int nw = warp & 3;            // 0..3
    const int M0 = mw * 32;
    const int N0 = nw * 32;
    const int m0 = (bid >> 5) * 128;
    const int n0 = (bid & 31) * 128;

    if (t < 128) biasS[t] = bias[n0 + t];

    const __half* Ag = Ah + (size_t)m0 * KDIM;
    const float*  Wg = W  + (size_t)n0 * KDIM;

    #define ISSUE_A(ktv, slot) do {                                            \
        const int _kt = (ktv);                                                 \
        const uint32_t _stg = sbase + (uint32_t)(slot) * TILE_B;               \
        _Pragma("unroll")                                                      \
        for (int _i = 0; _i < 2; _i++) {                                       \
            const int _c = _i * 512 + t;                                       \
            const int _r = _c >> 3;                                            \
            const int _c16 = _c & 7;                                           \
            cpasync16(_stg + (uint32_t)(_r * SROW + _c16 * 8) * 2,             \
                      Ag + (size_t)_r * KDIM + _kt * KT + _c16 * 8);           \
        }                                                                      \
    } while (0)

    const int rowL = t >> 4;   // 0..31
    const int col4 = t & 15;   // 0..15
    float4 wreg[4];

    #define LOAD_W(ktv) do {                                                   \
        _Pragma("unroll")                                                      \
        for (int _i = 0; _i < 4; _i++)                                         \
            wreg[_i] = *(const float4*)(Wg + (size_t)(rowL + 32 * _i) * KDIM   \
                                        + (ktv) * KT + col4 * 4);              \
    } while (0)

    #define STS_W(buf) do {                                                    \
        _Pragma("unroll")                                                      \
        for (int _i = 0; _i < 4; _i++) {                                       \
            __half2 _h0 = __floats2half2_rn(wreg[_i].x, wreg[_i].y);           \
            __half2 _h1 = __floats2half2_rn(wreg[_i].z, wreg[_i].w);           \
            uint32_t _ad = sbase + WF_OFF + (uint32_t)(buf) * TILE_B           \
                         + (uint32_t)((rowL + 32 * _i) * SROW + col4 * 4) * 2; \
            asm volatile("st.shared.v2.u32 [%0], {%1, %2};" :: "r"(_ad),       \
                         "r"(*(uint32_t*)&_h0), "r"(*(uint32_t*)&_h1));        \
        }                                                                      \
    } while (0)

    ISSUE_A(0, 0); CP_COMMIT();
    ISSUE_A(1, 1); CP_COMMIT();
    ISSUE_A(2, 2); CP_COMMIT();
    ISSUE_A(3, 3); CP_COMMIT();
    LOAD_W(0); STS_W(0);
    LOAD_W(1); STS_W(1);
    LOAD_W(2);

    const int g = lane >> 3, rin = lane & 7;
    const int rowA = M0 + (g & 1) * 8 + rin;
    const int colA = (g >> 1) * 8;
    const int rowB = N0 + (g >> 1) * 8 + rin;
    const int colB = (g & 1) * 8;

    float acc[2][4][4];
    #pragma unroll
    for (int i = 0; i < 2; i++)
        #pragma unroll
        for (int j = 0; j < 4; j++)
            #pragma unroll
            for (int k = 0; k < 4; k++) acc[i][j][k] = 0.0f;

    uint32_t aF[2][2][4], bF[2][2][4];

    #define LOADH(hh, buf, bAv, bWv) do {                                      \
        const int _kc = (hh) * 16;                                             \
        _Pragma("unroll")                                                      \
        for (int _mi = 0; _mi < 2; _mi++)                                      \
            ldsm_x4(aF[buf][_mi],                                              \
                    (bAv) + (uint32_t)((rowA + _mi * 16) * SROW + _kc + colA) * 2); \
        _Pragma("unroll")                                                      \
        for (int _j = 0; _j < 2; _j++)                                         \
            ldsm_x4(bF[buf][_j],                                               \
                    (bWv) + (uint32_t)((rowB + _j * 16) * SROW + _kc + colB) * 2);  \
    } while (0)

    #define COMPUTE_TILE(slotA, slotW) do {                                    \
        const uint32_t _bA = sbase + (uint32_t)(slotA) * TILE_B;               \
        const uint32_t _bW = sbase + WF_OFF + (uint32_t)(slotW) * TILE_B;      \
        LOADH(0, 0, _bA, _bW);                                                 \
        _Pragma("unroll")                                                      \
        for (int _h = 0; _h < 4; _h++) {                                       \
            const int _cur = _h & 1;                                           \
            if (_h < 3) LOADH(_h + 1, _cur ^ 1, _bA, _bW);                     \
            _Pragma("unroll")                                                  \
            for (int _mi = 0; _mi < 2; _mi++)                                  \
                _Pragma("unroll")                                              \
                for (int _nj = 0; _nj < 4; _nj++) {                            \
                    const int _jj = _nj >> 1, _pp = (_nj & 1) * 2;             \
                    mma16816h(acc[_mi][_nj], aF[_cur][_mi],                    \
                              bF[_cur][_jj][_pp], bF[_cur][_jj][_pp + 1]);     \
                }                                                              \
        }                                                                      \
    } while (0)

    int sA0 = 0, sA1 = 1, iA0 = 4, iA1 = 5;
    for (int kt = 0; kt < NT; kt += 2) {
        if (kt + 2 >= NT) cp_wait<0>(); else cp_wait<2>();
        __syncthreads();
        if (kt + 4 < NT) { ISSUE_A(kt + 4, iA0); CP_COMMIT(); }
        if (kt + 5 < NT) { ISSUE_A(kt + 5, iA1); CP_COMMIT(); }

        COMPUTE_TILE(sA0, kt & 3);
        if (kt + 2 < NT) {
            STS_W((kt + 2) & 3);
            LOAD_W(kt + 3);
        }
        COMPUTE_TILE(sA1, (kt + 1) & 3);
        if (kt + 2 < NT) STS_W((kt + 3) & 3);
        if (kt + 4 < NT) LOAD_W(kt + 4);

        sA0 += 2; if (sA0 >= NASLOT) sA0 -= NASLOT;
        sA1 += 2; if (sA1 >= NASLOT) sA1 -= NASLOT;
        iA0 += 2; if (iA0 >= NASLOT) iA0 -= NASLOT;
        iA1 += 2; if (iA1 >= NASLOT) iA1 -= NASLOT;
    }

    // epilogue: bias + tanh -> outputs; fid mode accumulates act4 dots
    const int r0l = lane >> 2;
    const int c0l = 2 * (lane & 3);
    float fs[4] = {0.0f, 0.0f, 0.0f, 0.0f};
    #pragma unroll
    for (int mi = 0; mi < 2; mi++) {
        #pragma unroll
        for (int nj = 0; nj < 4; nj++) {
            const int gnl = N0 + nj * 8 + c0l;
            const float b0 = biasS[gnl], b1 = biasS[gnl + 1];
            const int gm0 = m0 + M0 + mi * 16 + r0l;
            float v00 = tanhf(acc[mi][nj][0] + b0);
            float v01 = tanhf(acc[mi][nj][1] + b1);
            float v10 = tanhf(acc[mi][nj][2] + b0);
            float v11 = tanhf(acc[mi][nj][3] + b1);
            if (Ch != nullptr) {
                *(__half2*)(Ch + (size_t)gm0 * DIM + n0 + gnl) =
                    __floats2half2_rn(v00, v01);
                *(__half2*)(Ch + (size_t)(gm0 + 8) * DIM + n0 + gnl) =
                    __floats2half2_rn(v10, v11);
            }
            if (C != nullptr) {
                *(float2*)(C + (size_t)gm0 * DIM + n0 + gnl) = make_float2(v00, v01);
                *(float2*)(C + (size_t)(gm0 + 8) * DIM + n0 + gnl) = make_float2(v10, v11);
            }
            if (wout != nullptr) {
                const size_t o0 = (size_t)gm0 * DIM + n0 + gnl;
                const size_t o1 = (size_t)(gm0 + 8) * DIM + n0 + gnl;
                float2 x1a = __half22float2(*(const __half2*)(f1 + o0));
                float2 x2a = __half22float2(*(const __half2*)(f2 + o0));
                float2 x3a = __half22float2(*(const __half2*)(f3 + o0));
                float2 x1b = __half22float2(*(const __half2*)(f1 + o1));
                float2 x2b = __half22float2(*(const __half2*)(f2 + o1));
                float2 x3b = __half22float2(*(const __half2*)(f3 + o1));
                fs[0] += x1a.x * v00 + x1a.y * v01 + x1b.x * v10 + x1b.y * v11;
                fs[1] += x2a.x * v00 + x2a.y * v01 + x2b.x * v10 + x2b.y * v11;
                fs[2] += x3a.x * v00 + x3a.y * v01 + x3b.x * v10 + x3b.y * v11;
                fs[3] += v00 * v00 + v01 * v01 + v10 * v10 + v11 * v11;
            }
        }
    }

    if (wout == nullptr) return;

    // block-reduce the 4 act4 dots and arrive
    #pragma unroll
    for (int k = 0; k < 4; k++)
        #pragma unroll
        for (int off = 16; off > 0; off >>= 1)
            fs[k] += __shfl_down_sync(0xFFFFFFFFu, fs[k], off);
    if (lane == 0)
        #pragma unroll
        for (int k = 0; k < 4; k++) ws4[warp][k] = fs[k];
    __syncthreads();
    if (t == 0) {
        #pragma unroll
        for (int k = 0; k < 4; k++) {
            float acc2 = 0.0f;
            for (int w = 0; w < 16; w++) acc2 += ws4[w][k];
            g_partials[256 + bid * 4 + k] = acc2;
        }
        __threadfence();
        unsigned int v = atomicAdd(&g_ticket, 1u);
        lastFlag = (v == 147u) ? 1u : 0u;
    }
    __syncthreads();
    if (lastFlag == 0u) return;
    }

finalize:
    // ---- last of 148 blocks: combine partials -> weights ----
    {
        const int lid = t & 31;
        const int w = t >> 5;
        // dots order: 0:(11) 1:(12) 2:(13) 3:(14) 4:(22) 5:(23) 6:(24)
        //             7:(33) 8:(34) 9:(44)
        if (w < 10) {
            const int fromB[10] = {0, 0, 0, 1, 0, 0, 1, 0, 1, 1};
            const int pos[10]   = {0, 1, 2, 0, 3, 4, 1, 5, 2, 3};
            double acc = 0.0;
            if (fromB[w]) {
                for (int p = lid; p < 128; p += 32)
                    acc += (double)g_partials[256 + p * 4 + pos[w]];
            } else {
                for (int p = lid; p < 20; p += 32)
                    acc += (double)g_partials[p * 6 + pos[w]];
            }
            #pragma unroll
            for (int off = 16; off > 0; off >>= 1)
                acc += __shfl_down_sync(0xFFFFFFFFu, acc, off);
            if (lid == 0) dots[w] = acc;
        }
        __syncthreads();
        if (t < 16) {
            int i = t >> 2, j = t & 3;
            int ii = i < j ? i : j, jj = i < j ? j : i;
            const int base[4] = {0, 4, 7, 9};
            double dij = dots[base[ii] + (jj - ii)];
            double dii = dots[base[ii]];
            double djj = dots[base[jj]];
            double ni = sqrt(dii) + 1e-12;
            double nj = sqrt(djj) + 1e-12;
            double sh = dij / (ni * nj);
            double fid = sh * sh;
            wout[t] = (fid >= 0.8 && i != j) ? 1.0f : 0.0f;
        }
        if (t == 0) g_ticket = 0u;   // reset for next graph replay
    }
}

// ---------------------------------------------------------------------------
// kernel_launch
//   0 conv, 1 attn_layer1, 2 gemm1, 3 gemm2, 4 gemm3+fid (148 blocks)
// ---------------------------------------------------------------------------
extern "C" void kernel_launch(void* const* d_in, const int* in_sizes, int n_in,
                              void* d_out, int out_size) {
    const float* x   = (const float*)d_in[0];
    const float* cw  = (const float*)d_in[1];
    const float* cb  = (const float*)d_in[2];
    const float* rot = (const float*)d_in[3];
    const float* ent = (const float*)d_in[4];
    const float* W1  = (const float*)d_in[5];
    const float* b1  = (const float*)d_in[6];
    const float* W2  = (const float*)d_in[7];
    const float* b2  = (const float*)d_in[8];
    const float* W3  = (const float*)d_in[9];
    const float* b3  = (const float*)d_in[10];
    const float* W4  = (const float*)d_in[11];
    const float* b4  = (const float*)d_in[12];
    float* out = (float*)d_out;

    float* gc;
    __half* ah;
    cudaGetSymbolAddress((void**)&gc, g_c);
    cudaGetSymbolAddress((void**)&ah, g_ah);

    cudaFuncSetAttribute(gemm_mma_kernel,
                         cudaFuncAttributeMaxDynamicSharedMemorySize, SMEM_REQ);

    __half* a1 = ah + 0 * (size_t)OUTN;
    __half* a2 = ah + 1 * (size_t)OUTN;
    __half* a3 = ah + 2 * (size_t)OUTN;

    conv_kernel<<<BB, 256>>>(x, cw, cb, gc);                         // 0
    attn_layer1_kernel<<<1024, 256>>>(gc, rot, ent, W1, b1, a1);     // 1
    gemm_mma_kernel<<<128, 512, SMEM_REQ>>>(                         // 2
        a1, W2, b2, nullptr, a2,
        nullptr, nullptr, nullptr, nullptr);
    gemm_mma_kernel<<<128, 512, SMEM_REQ>>>(                         // 3
        a2, W3, b3, nullptr, a3,
        nullptr, nullptr, nullptr, nullptr);
    gemm_mma_kernel<<<148, 512, SMEM_REQ>>>(                         // 4
        a3, W4, b4, out, nullptr,
        a1, a2, a3, out + OUTN);
}